// round 13
// baseline (speedup 1.0000x reference)
#include <cuda_runtime.h>
#include <cuda_fp16.h>
#include <cstdint>

// ===================== problem dims (fixed) =====================
#define M_DIM 8192
#define N_DIM 4096
#define K_DIM 4096

// CTA tile 128(M) x 256(N), K-stage 64 halves (128B rows, SW128 swizzle)
// PERSISTENT CTAs, 4-stage cp.async ring. Completion tracked by
// commit_group/wait_group (per-thread, no shared resource); mbarriers are
// reduced to ONE arrive per warp (init=8) - R12 paid ~512 serialized
// mbarrier ops per kt, this pays 16.
#define TILE_M 128
#define TILE_N 256
#define KT 64
#define NK (K_DIM / KT)            // 64  (iterations per tile)
#define STAGES 4
#define NTHREADS 256               // 8 warps: 2(M) x 4(N), warp tile 64x64
#define NTILES 1024                // 64 mtiles x 16 ntiles

// ===================== static fp16 scratch (inputs arrive as f32) ==========
__device__ __half g_A16[(size_t)M_DIM * K_DIM];   // 64 MiB
__device__ __half g_W16[(size_t)N_DIM * K_DIM];   // 32 MiB

// ===================== SMEM layout (bytes) ======================
#define SM_FULL(s)  ((s) * 8)            // 0..31
#define SM_EMPTY(s) (32 + (s) * 8)       // 32..63
#define SM_STAGE0 1024
#define A_STAGE_BYTES (TILE_M * 128)     // 16384
#define B_STAGE_BYTES (TILE_N * 128)     // 32768
#define STAGE_BYTES (A_STAGE_BYTES + B_STAGE_BYTES)   // 49152
#define SM_A(s) (SM_STAGE0 + (s) * STAGE_BYTES)
#define SM_B(s) (SM_A(s) + A_STAGE_BYTES)
#define SMEM_TOTAL (SM_STAGE0 + STAGES * STAGE_BYTES) // 197632

// ===================== device helpers =====================
static __device__ __forceinline__ uint32_t smem_u32(const void* p) {
    uint32_t a;
    asm("{ .reg .u64 t; cvta.to.shared.u64 t, %1; cvt.u32.u64 %0, t; }"
        : "=r"(a) : "l"(p));
    return a;
}

static __device__ __forceinline__ uint32_t sw128(uint32_t off) {
    return off ^ ((off >> 3) & 0x70);
}

static __device__ __forceinline__ void cp_async16(uint32_t saddr, const void* gaddr) {
    asm volatile("cp.async.cg.shared.global [%0], [%1], 16;"
        :: "r"(saddr), "l"(gaddr) : "memory");
}
#define CP_COMMIT() asm volatile("cp.async.commit_group;" ::: "memory")
#define CP_WAIT(n)  asm volatile("cp.async.wait_group %0;" :: "n"(n) : "memory")

#define MBARRIER_INIT(addr, cnt) \
    asm volatile("mbarrier.init.shared.b64 [%0], %1;" \
        :: "r"((uint32_t)(addr)), "r"((uint32_t)(cnt)) : "memory")

#define MBARRIER_ARRIVE(addr) \
    asm volatile("mbarrier.arrive.release.cta.shared.b64 _, [%0];" \
        :: "r"((uint32_t)(addr)) : "memory")

#define MBARRIER_WAIT_PARITY(addr, parity) do {                                   \
    uint32_t _mbar = (uint32_t)(addr);                                            \
    uint32_t _par  = (uint32_t)(parity);                                          \
    uint32_t _done;                                                               \
    asm volatile(                                                                 \
        "{\n\t.reg .pred p;\n\t"                                                  \
        "mbarrier.try_wait.parity.acquire.cta.shared::cta.b64 p, [%1], %2;\n\t"   \
        "selp.b32 %0, 1, 0, p;\n\t}"                                              \
        : "=r"(_done) : "r"(_mbar), "r"(_par) : "memory");                        \
    if (!_done) {                                                                 \
        asm volatile(                                                             \
            "{\n\t.reg .pred P1;\n\t"                                             \
            "WAIT_LOOP_%=:\n\t"                                                   \
            "mbarrier.try_wait.parity.acquire.cta.shared::cta.b64 P1, [%0], %1, 0x989680;\n\t" \
            "@P1 bra.uni WAIT_DONE_%=;\n\t"                                       \
            "bra.uni WAIT_LOOP_%=;\n\t"                                           \
            "WAIT_DONE_%=:\n\t}"                                                  \
            :: "r"(_mbar), "r"(_par) : "memory");                                 \
    }                                                                             \
} while (0)

static __device__ __forceinline__ void ldsm_x4(uint32_t addr,
    uint32_t& r0, uint32_t& r1, uint32_t& r2, uint32_t& r3) {
    asm volatile("ldmatrix.sync.aligned.m8n8.x4.shared.b16 {%0,%1,%2,%3}, [%4];"
        : "=r"(r0), "=r"(r1), "=r"(r2), "=r"(r3) : "r"(addr));
}

static __device__ __forceinline__ void mma16816(
    float& c0, float& c1, float& c2, float& c3,
    uint32_t a0, uint32_t a1, uint32_t a2, uint32_t a3,
    uint32_t b0, uint32_t b1) {
    asm volatile(
        "mma.sync.aligned.m16n8k16.row.col.f32.f16.f16.f32 "
        "{%0,%1,%2,%3}, {%4,%5,%6,%7}, {%8,%9}, {%0,%1,%2,%3};"
        : "+f"(c0), "+f"(c1), "+f"(c2), "+f"(c3)
        : "r"(a0), "r"(a1), "r"(a2), "r"(a3), "r"(b0), "r"(b1));
}

static __device__ __forceinline__ float h_round(float x) {
    return __half2float(__float2half_rn(x));
}

// ===================== fused f32 -> f16 conversion (single launch) =========
#define NA4 ((M_DIM * K_DIM) / 4)          // 8388608
#define NW4 ((N_DIM * K_DIM) / 4)          // 4194304
__global__ void __launch_bounds__(256) cvt_all_f32_to_f16(
    const float4* __restrict__ inA, const float4* __restrict__ inW,
    __half* __restrict__ oA, __half* __restrict__ oW) {
    const int i = blockIdx.x * blockDim.x + threadIdx.x;
    const float4* src; __half* dst; int j;
    if (i < NA4) { src = inA; dst = oA; j = i; }
    else         { src = inW; dst = oW; j = i - NA4; }
    const float4 v = src[j];
    const __half2 h0 = __floats2half2_rn(v.x, v.y);
    const __half2 h1 = __floats2half2_rn(v.z, v.w);
    uint2 pk;
    pk.x = reinterpret_cast<const uint32_t&>(h0);
    pk.y = reinterpret_cast<const uint32_t&>(h1);
    *(uint2*)(dst + (size_t)j * 4) = pk;
}

// ===================== GEMM kernel (persistent) =====================
// 256 threads = 8 warps as 2(M) x 4(N); warp tile 64x64, f32 accumulate.
// Completion protocol per iteration `it`:
//   producer: [wait EMPTY(slot) if reused] issue cp.asyncs; ALWAYS commit
//             one group (empty commit when no load left -> constant depth).
//   consumer: cp.async.wait_group 3 (own stage-`it` loads done: exactly 3
//             newer groups exist) -> syncwarp -> lane0 arrive FULL (init 8)
//             -> wait FULL parity -> MMA -> syncwarp -> lane0 arrive EMPTY.
__global__ void __launch_bounds__(NTHREADS, 1) linear_f16_hmma(
    const float* __restrict__ bias,  // [4096] f32
    float* __restrict__ out)         // [8192, 4096] f32
{
    extern __shared__ char smem[];
    const uint32_t sb = smem_u32(smem);
    const int tid  = threadIdx.x;
    const int wid  = tid >> 5;
    const int lane = tid & 31;
    const int warp_m = wid & 1;      // 0..1
    const int warp_n = wid >> 1;     // 0..3
    const int bid  = blockIdx.x;
    const int nsm  = gridDim.x;

    // tiles handled by this CTA: bid, bid+nsm, ... < NTILES
    const int ntiles_cta = (NTILES - bid + nsm - 1) / nsm;
    const int niter = ntiles_cta * NK;

    // ---- init: mbarriers (tid 0), ONE arrival per warp ----
    if (tid == 0) {
        #pragma unroll
        for (int s = 0; s < STAGES; ++s) {
            MBARRIER_INIT(sb + SM_FULL(s),  8);
            MBARRIER_INIT(sb + SM_EMPTY(s), 8);
        }
    }
    __syncthreads();   // barriers visible; only CTA-wide sync in kernel

    const char* const Aall = (const char*)g_A16;
    const char* const Ball = (const char*)g_W16;

    // -------- stage loader for flat iteration `it`: 3072 x 16B chunks ------
    auto load_stage = [&](int it) {
        const int s  = it & (STAGES - 1);
        const int lt = it >> 6;                 // local tile index
        const int kt = it & (NK - 1);
        const int gt = bid + lt * nsm;          // global tile
        const int mt = gt >> 4, nt = gt & 15;
        const char* Abase = Aall + (size_t)(mt * TILE_M) * (K_DIM * 2);
        const char* Bbase = Ball + (size_t)(nt * TILE_N) * (K_DIM * 2);
        const size_t kbyte = (size_t)kt * (KT * 2);
        const uint32_t a_s = sb + SM_A(s);
        const uint32_t b_s = sb + SM_B(s);
        #pragma unroll
        for (int i = 0; i < 12; ++i) {
            const int c = tid + i * NTHREADS;
            if (c < 1024) {                       // A: 128 rows x 8 chunks
                const int row = c >> 3, ci = c & 7;
                const char* g = Abase + (size_t)row * (K_DIM * 2) + kbyte + ci * 16;
                cp_async16(a_s + sw128((uint32_t)(row * 128 + ci * 16)), g);
            } else {                              // B: 256 rows x 8 chunks
                const int c2 = c - 1024;
                const int row = c2 >> 3, ci = c2 & 7;
                const char* g = Bbase + (size_t)row * (K_DIM * 2) + kbyte + ci * 16;
                cp_async16(b_s + sw128((uint32_t)(row * 128 + ci * 16)), g);
            }
        }
    };

    // -------- f32 accumulators: warp tile 64(M) x 64(N) --------
    float acc[4][8][4];
    #pragma unroll
    for (int mf = 0; mf < 4; ++mf)
        #pragma unroll
        for (int nf = 0; nf < 8; ++nf)
            #pragma unroll
            for (int i = 0; i < 4; ++i) acc[mf][nf][i] = 0.f;

    // per-lane ldmatrix address components
    const int a_row  = warp_m * 64 + (lane & 15);
    const int a_koff = (lane >> 4) * 16;
    const int b_row  = warp_n * 64 + ((lane >> 4) << 3) + (lane & 7);
    const int b_koff = ((lane >> 3) & 1) * 16;

    // -------- prologue: fill 3 stages, one commit group each --------
    load_stage(0); CP_COMMIT();
    load_stage(1); CP_COMMIT();
    load_stage(2); CP_COMMIT();

    // -------- flat main loop over all tiles: ring never drains --------
    for (int it = 0; it < niter; ++it) {
        // produce iteration it+3 (slot last consumed as it-1)
        const int ld = it + 3;
        if (ld < niter) {
            if (ld >= STAGES) {   // slot has a previous lap: wait for readers
                MBARRIER_WAIT_PARITY(sb + SM_EMPTY(ld & (STAGES - 1)),
                                     ((ld >> 2) - 1) & 1);
            }
            load_stage(ld);
        }
        CP_COMMIT();   // ALWAYS: keeps group depth constant (empty at tail)

        // consume iteration it: own loads done after wait_group 3
        CP_WAIT(3);
        __syncwarp();
        if (lane == 0) MBARRIER_ARRIVE(sb + SM_FULL(it & (STAGES - 1)));
        const int s = it & (STAGES - 1);
        MBARRIER_WAIT_PARITY(sb + SM_FULL(s), (it >> 2) & 1);

        const uint32_t aB = sb + SM_A(s);
        const uint32_t bB = sb + SM_B(s);

        #pragma unroll
        for (int kk = 0; kk < 4; ++kk) {
            uint32_t a[4][4];
            #pragma unroll
            for (int mf = 0; mf < 4; ++mf) {
                const uint32_t addr = aB +
                    sw128((uint32_t)((a_row + mf * 16) * 128 + kk * 32 + a_koff));
                ldsm_x4(addr, a[mf][0], a[mf][1], a[mf][2], a[mf][3]);
            }
            uint32_t b[4][4];
            #pragma unroll
            for (int nf2 = 0; nf2 < 4; ++nf2) {
                const uint32_t addr = bB +
                    sw128((uint32_t)((b_row + nf2 * 16) * 128 + kk * 32 + b_koff));
                ldsm_x4(addr, b[nf2][0], b[nf2][1], b[nf2][2], b[nf2][3]);
            }
            #pragma unroll
            for (int mf = 0; mf < 4; ++mf) {
                #pragma unroll
                for (int nf = 0; nf < 8; ++nf) {
                    const uint32_t b0 = b[nf >> 1][(nf & 1) * 2 + 0];
                    const uint32_t b1 = b[nf >> 1][(nf & 1) * 2 + 1];
                    mma16816(acc[mf][nf][0], acc[mf][nf][1],
                             acc[mf][nf][2], acc[mf][nf][3],
                             a[mf][0], a[mf][1], a[mf][2], a[mf][3], b0, b1);
                }
            }
        }

        // done reading this stage: one arrive per warp
        __syncwarp();
        if (lane == 0) MBARRIER_ARRIVE(sb + SM_EMPTY(s));

        // -------- tile boundary: epilogue + acc reset --------
        if ((it & (NK - 1)) == NK - 1) {
            const int gt = bid + (it >> 6) * nsm;
            const int m0 = (gt >> 4) * TILE_M;
            const int n0 = (gt & 15) * TILE_N;

            const int row0 = m0 + warp_m * 64 + (lane >> 2);
            const int col0 = n0 + warp_n * 64 + (lane & 3) * 2;
            const int bcol = warp_n * 64 + (lane & 3) * 2;

            #pragma unroll
            for (int mf = 0; mf < 4; ++mf) {
                #pragma unroll
                for (int nf = 0; nf < 8; ++nf) {
                    const float2 bv = *(const float2*)(bias + n0 + bcol + nf * 8);
                    const int r = row0 + mf * 16;
                    const int c = col0 + nf * 8;
                    float2 lo, hi;
                    lo.x = h_round(acc[mf][nf][0] + bv.x);
                    lo.y = h_round(acc[mf][nf][1] + bv.y);
                    hi.x = h_round(acc[mf][nf][2] + bv.x);
                    hi.y = h_round(acc[mf][nf][3] + bv.y);
                    *(float2*)(out + (size_t)r * N_DIM + c)       = lo;
                    *(float2*)(out + (size_t)(r + 8) * N_DIM + c) = hi;
                    acc[mf][nf][0] = 0.f; acc[mf][nf][1] = 0.f;
                    acc[mf][nf][2] = 0.f; acc[mf][nf][3] = 0.f;
                }
            }
        }
    }
}

// ===================== host launcher =====================
extern "C" void kernel_launch(void* const* d_in, const int* in_sizes, int n_in,
                              void* d_out, int out_size) {
    (void)in_sizes; (void)n_in; (void)out_size;
    const float* x = (const float*)d_in[0];   // [8192,4096] f32
    const float* w = (const float*)d_in[1];   // [4096,4096] f32
    const float* b = (const float*)d_in[2];   // [4096] f32
    float* y = (float*)d_out;                 // [8192,4096] f32

    static __half* a16_ptr = nullptr;
    static __half* w16_ptr = nullptr;
    static int nsm = 0;
    if (!a16_ptr) {
        cudaGetSymbolAddress((void**)&a16_ptr, g_A16);
        cudaGetSymbolAddress((void**)&w16_ptr, g_W16);
        cudaDeviceGetAttribute(&nsm, cudaDevAttrMultiProcessorCount, 0);
        if (nsm <= 0 || nsm > NTILES) nsm = 148;
    }

    cvt_all_f32_to_f16<<<(NA4 + NW4) / 256, 256>>>(
        (const float4*)x, (const float4*)w, a16_ptr, w16_ptr);

    cudaFuncSetAttribute(linear_f16_hmma,
                         cudaFuncAttributeMaxDynamicSharedMemorySize, SMEM_TOTAL);
    linear_f16_hmma<<<nsm, NTHREADS, SMEM_TOTAL>>>(b, y);
}

// round 14
// speedup vs baseline: 1.0154x; 1.0154x over previous
#include <cuda_runtime.h>
#include <cuda_fp16.h>
#include <cstdint>

// ===================== problem dims (fixed) =====================
#define M_DIM 8192
#define N_DIM 4096
#define K_DIM 4096

// CTA tile 128(M) x 256(N), K-stage 64 halves (128B rows, SW128 swizzle)
// PERSISTENT CTAs, 4-stage cp.async ring, R12 sync protocol (CTA-wide
// noinc FULL + per-thread EMPTY arrives). NEW vs R12: the 12 cp.asyncs
// per thread are interleaved into the 4 kk MMA blocks (3 each) so the
// LSU burst executes in the MMA shadow instead of before the consume wait.
#define TILE_M 128
#define TILE_N 256
#define KT 64
#define NK (K_DIM / KT)            // 64  (iterations per tile)
#define STAGES 4
#define NTHREADS 256               // 8 warps: 2(M) x 4(N), warp tile 64x64
#define NTILES 1024                // 64 mtiles x 16 ntiles

// ===================== static fp16 scratch (inputs arrive as f32) ==========
__device__ __half g_A16[(size_t)M_DIM * K_DIM];   // 64 MiB
__device__ __half g_W16[(size_t)N_DIM * K_DIM];   // 32 MiB

// ===================== SMEM layout (bytes) ======================
#define SM_FULL(s)  ((s) * 8)            // 0..31
#define SM_EMPTY(s) (32 + (s) * 8)       // 32..63
#define SM_STAGE0 1024
#define A_STAGE_BYTES (TILE_M * 128)     // 16384
#define B_STAGE_BYTES (TILE_N * 128)     // 32768
#define STAGE_BYTES (A_STAGE_BYTES + B_STAGE_BYTES)   // 49152
#define SM_A(s) (SM_STAGE0 + (s) * STAGE_BYTES)
#define SM_B(s) (SM_A(s) + A_STAGE_BYTES)
#define SMEM_TOTAL (SM_STAGE0 + STAGES * STAGE_BYTES) // 197632

// ===================== device helpers =====================
static __device__ __forceinline__ uint32_t smem_u32(const void* p) {
    uint32_t a;
    asm("{ .reg .u64 t; cvta.to.shared.u64 t, %1; cvt.u32.u64 %0, t; }"
        : "=r"(a) : "l"(p));
    return a;
}

static __device__ __forceinline__ uint32_t sw128(uint32_t off) {
    return off ^ ((off >> 3) & 0x70);
}

static __device__ __forceinline__ void cp_async16(uint32_t saddr, const void* gaddr) {
    asm volatile("cp.async.cg.shared.global [%0], [%1], 16;"
        :: "r"(saddr), "l"(gaddr) : "memory");
}

#define MBARRIER_INIT(addr, cnt) \
    asm volatile("mbarrier.init.shared.b64 [%0], %1;" \
        :: "r"((uint32_t)(addr)), "r"((uint32_t)(cnt)) : "memory")

#define MBARRIER_ARRIVE(addr) \
    asm volatile("mbarrier.arrive.shared.b64 _, [%0];" \
        :: "r"((uint32_t)(addr)) : "memory")

// arrive (counting against the INIT count: .noinc) when all this thread's
// prior cp.asyncs have completed.
#define CPASYNC_MBAR_ARRIVE(addr) \
    asm volatile("cp.async.mbarrier.arrive.noinc.shared::cta.b64 [%0];" \
        :: "r"((uint32_t)(addr)) : "memory")

#define MBARRIER_WAIT_PARITY(addr, parity) do {                                   \
    uint32_t _mbar = (uint32_t)(addr);                                            \
    uint32_t _par  = (uint32_t)(parity);                                          \
    uint32_t _done;                                                               \
    asm volatile(                                                                 \
        "{\n\t.reg .pred p;\n\t"                                                  \
        "mbarrier.try_wait.parity.acquire.cta.shared::cta.b64 p, [%1], %2;\n\t"   \
        "selp.b32 %0, 1, 0, p;\n\t}"                                              \
        : "=r"(_done) : "r"(_mbar), "r"(_par) : "memory");                        \
    if (!_done) {                                                                 \
        asm volatile(                                                             \
            "{\n\t.reg .pred P1;\n\t"                                             \
            "WAIT_LOOP_%=:\n\t"                                                   \
            "mbarrier.try_wait.parity.acquire.cta.shared::cta.b64 P1, [%0], %1, 0x989680;\n\t" \
            "@P1 bra.uni WAIT_DONE_%=;\n\t"                                       \
            "bra.uni WAIT_LOOP_%=;\n\t"                                           \
            "WAIT_DONE_%=:\n\t}"                                                  \
            :: "r"(_mbar), "r"(_par) : "memory");                                 \
    }                                                                             \
} while (0)

static __device__ __forceinline__ void ldsm_x4(uint32_t addr,
    uint32_t& r0, uint32_t& r1, uint32_t& r2, uint32_t& r3) {
    asm volatile("ldmatrix.sync.aligned.m8n8.x4.shared.b16 {%0,%1,%2,%3}, [%4];"
        : "=r"(r0), "=r"(r1), "=r"(r2), "=r"(r3) : "r"(addr));
}

static __device__ __forceinline__ void mma16816(
    float& c0, float& c1, float& c2, float& c3,
    uint32_t a0, uint32_t a1, uint32_t a2, uint32_t a3,
    uint32_t b0, uint32_t b1) {
    asm volatile(
        "mma.sync.aligned.m16n8k16.row.col.f32.f16.f16.f32 "
        "{%0,%1,%2,%3}, {%4,%5,%6,%7}, {%8,%9}, {%0,%1,%2,%3};"
        : "+f"(c0), "+f"(c1), "+f"(c2), "+f"(c3)
        : "r"(a0), "r"(a1), "r"(a2), "r"(a3), "r"(b0), "r"(b1));
}

static __device__ __forceinline__ float h_round(float x) {
    return __half2float(__float2half_rn(x));
}

// ===================== fused f32 -> f16 conversion (single launch) =========
#define NA4 ((M_DIM * K_DIM) / 4)          // 8388608
#define NW4 ((N_DIM * K_DIM) / 4)          // 4194304
__global__ void __launch_bounds__(256) cvt_all_f32_to_f16(
    const float4* __restrict__ inA, const float4* __restrict__ inW,
    __half* __restrict__ oA, __half* __restrict__ oW) {
    const int i = blockIdx.x * blockDim.x + threadIdx.x;
    const float4* src; __half* dst; int j;
    if (i < NA4) { src = inA; dst = oA; j = i; }
    else         { src = inW; dst = oW; j = i - NA4; }
    const float4 v = src[j];
    const __half2 h0 = __floats2half2_rn(v.x, v.y);
    const __half2 h1 = __floats2half2_rn(v.z, v.w);
    uint2 pk;
    pk.x = reinterpret_cast<const uint32_t&>(h0);
    pk.y = reinterpret_cast<const uint32_t&>(h1);
    *(uint2*)(dst + (size_t)j * 4) = pk;
}

// ===================== GEMM kernel (persistent) =====================
// 256 threads = 8 warps as 2(M) x 4(N); warp tile 64x64, f32 accumulate.
__global__ void __launch_bounds__(NTHREADS, 1) linear_f16_hmma(
    const float* __restrict__ bias,  // [4096] f32
    float* __restrict__ out)         // [8192, 4096] f32
{
    extern __shared__ char smem[];
    const uint32_t sb = smem_u32(smem);
    const int tid  = threadIdx.x;
    const int wid  = tid >> 5;
    const int lane = tid & 31;
    const int warp_m = wid & 1;      // 0..1
    const int warp_n = wid >> 1;     // 0..3
    const int bid  = blockIdx.x;
    const int nsm  = gridDim.x;

    // tiles handled by this CTA: bid, bid+nsm, ... < NTILES
    const int ntiles_cta = (NTILES - bid + nsm - 1) / nsm;
    const int niter = ntiles_cta * NK;

    // ---- init: mbarriers (tid 0) ----
    if (tid == 0) {
        #pragma unroll
        for (int s = 0; s < STAGES; ++s) {
            MBARRIER_INIT(sb + SM_FULL(s),  NTHREADS);
            MBARRIER_INIT(sb + SM_EMPTY(s), NTHREADS);
        }
    }
    __syncthreads();   // barriers visible; only CTA-wide sync in kernel

    const char* const Aall = (const char*)g_A16;
    const char* const Ball = (const char*)g_W16;

    // ------ per-iteration global base pointers for the producer ------
    auto stage_bases = [&](int it, const char*& Abase, const char*& Bbase,
                           size_t& kbyte, uint32_t& a_s, uint32_t& b_s) {
        const int s  = it & (STAGES - 1);
        const int lt = it >> 6;                 // local tile index
        const int kt = it & (NK - 1);
        const int gt = bid + lt * nsm;          // global tile
        const int mt = gt >> 4, nt = gt & 15;
        Abase = Aall + (size_t)(mt * TILE_M) * (K_DIM * 2);
        Bbase = Ball + (size_t)(nt * TILE_N) * (K_DIM * 2);
        kbyte = (size_t)kt * (KT * 2);
        a_s = sb + SM_A(s);
        b_s = sb + SM_B(s);
    };

    // issue chunks [3p, 3p+3) of a stage (3 of this thread's 12)
    auto load_part = [&](const char* Abase, const char* Bbase, size_t kbyte,
                         uint32_t a_s, uint32_t b_s, int p) {
        #pragma unroll
        for (int i = 3 * p; i < 3 * p + 3; ++i) {
            const int c = tid + i * NTHREADS;
            if (c < 1024) {                       // A: 128 rows x 8 chunks
                const int row = c >> 3, ci = c & 7;
                const char* g = Abase + (size_t)row * (K_DIM * 2) + kbyte + ci * 16;
                cp_async16(a_s + sw128((uint32_t)(row * 128 + ci * 16)), g);
            } else {                              // B: 256 rows x 8 chunks
                const int c2 = c - 1024;
                const int row = c2 >> 3, ci = c2 & 7;
                const char* g = Bbase + (size_t)row * (K_DIM * 2) + kbyte + ci * 16;
                cp_async16(b_s + sw128((uint32_t)(row * 128 + ci * 16)), g);
            }
        }
    };

    // full stage load (prologue only)
    auto load_stage = [&](int it) {
        const char* Ab; const char* Bb; size_t kb; uint32_t as_, bs_;
        stage_bases(it, Ab, Bb, kb, as_, bs_);
        #pragma unroll
        for (int p = 0; p < 4; ++p) load_part(Ab, Bb, kb, as_, bs_, p);
        CPASYNC_MBAR_ARRIVE(sb + SM_FULL(it & (STAGES - 1)));
    };

    // -------- f32 accumulators: warp tile 64(M) x 64(N) --------
    float acc[4][8][4];
    #pragma unroll
    for (int mf = 0; mf < 4; ++mf)
        #pragma unroll
        for (int nf = 0; nf < 8; ++nf)
            #pragma unroll
            for (int i = 0; i < 4; ++i) acc[mf][nf][i] = 0.f;

    // per-lane ldmatrix address components
    const int a_row  = warp_m * 64 + (lane & 15);
    const int a_koff = (lane >> 4) * 16;
    const int b_row  = warp_n * 64 + ((lane >> 4) << 3) + (lane & 7);
    const int b_koff = ((lane >> 3) & 1) * 16;

    // -------- prologue: fill 3 stages --------
    if (0 < niter) load_stage(0);
    if (1 < niter) load_stage(1);
    if (2 < niter) load_stage(2);

    // -------- flat main loop over all tiles --------
    for (int it = 0; it < niter; ++it) {
        // producer setup for iteration it+3 (issue is interleaved below)
        const int ld = it + 3;
        const bool do_load = (ld < niter);
        const char* pA = nullptr; const char* pB = nullptr;
        size_t pkb = 0; uint32_t pas = 0, pbs = 0;
        if (do_load) {
            if (ld >= STAGES) {   // slot has a previous lap: wait for readers
                MBARRIER_WAIT_PARITY(sb + SM_EMPTY(ld & (STAGES - 1)),
                                     ((ld >> 2) - 1) & 1);
            }
            stage_bases(ld, pA, pB, pkb, pas, pbs);
        }

        // consume iteration it
        const int s = it & (STAGES - 1);
        MBARRIER_WAIT_PARITY(sb + SM_FULL(s), (it >> 2) & 1);

        const uint32_t aB = sb + SM_A(s);
        const uint32_t bB = sb + SM_B(s);

        #pragma unroll
        for (int kk = 0; kk < 4; ++kk) {
            // interleave 3 of this thread's 12 cp.asyncs into each kk block
            if (do_load) load_part(pA, pB, pkb, pas, pbs, kk);

            uint32_t a[4][4];
            #pragma unroll
            for (int mf = 0; mf < 4; ++mf) {
                const uint32_t addr = aB +
                    sw128((uint32_t)((a_row + mf * 16) * 128 + kk * 32 + a_koff));
                ldsm_x4(addr, a[mf][0], a[mf][1], a[mf][2], a[mf][3]);
            }
            uint32_t b[4][4];
            #pragma unroll
            for (int nf2 = 0; nf2 < 4; ++nf2) {
                const uint32_t addr = bB +
                    sw128((uint32_t)((b_row + nf2 * 16) * 128 + kk * 32 + b_koff));
                ldsm_x4(addr, b[nf2][0], b[nf2][1], b[nf2][2], b[nf2][3]);
            }
            #pragma unroll
            for (int mf = 0; mf < 4; ++mf) {
                #pragma unroll
                for (int nf = 0; nf < 8; ++nf) {
                    const uint32_t b0 = b[nf >> 1][(nf & 1) * 2 + 0];
                    const uint32_t b1 = b[nf >> 1][(nf & 1) * 2 + 1];
                    mma16816(acc[mf][nf][0], acc[mf][nf][1],
                             acc[mf][nf][2], acc[mf][nf][3],
                             a[mf][0], a[mf][1], a[mf][2], a[mf][3], b0, b1);
                }
            }
        }

        // producer arrive (after all 12 chunks issued), consumer arrive
        if (do_load) CPASYNC_MBAR_ARRIVE(sb + SM_FULL(ld & (STAGES - 1)));
        MBARRIER_ARRIVE(sb + SM_EMPTY(s));

        // -------- tile boundary: epilogue + acc reset --------
        if ((it & (NK - 1)) == NK - 1) {
            const int gt = bid + (it >> 6) * nsm;
            const int m0 = (gt >> 4) * TILE_M;
            const int n0 = (gt & 15) * TILE_N;

            const int row0 = m0 + warp_m * 64 + (lane >> 2);
            const int col0 = n0 + warp_n * 64 + (lane & 3) * 2;
            const int bcol = warp_n * 64 + (lane & 3) * 2;

            #pragma unroll
            for (int mf = 0; mf < 4; ++mf) {
                #pragma unroll
                for (int nf = 0; nf < 8; ++nf) {
                    const float2 bv = *(const float2*)(bias + n0 + bcol + nf * 8);
                    const int r = row0 + mf * 16;
                    const int c = col0 + nf * 8;
                    float2 lo, hi;
                    lo.x = h_round(acc[mf][nf][0] + bv.x);
                    lo.y = h_round(acc[mf][nf][1] + bv.y);
                    hi.x = h_round(acc[mf][nf][2] + bv.x);
                    hi.y = h_round(acc[mf][nf][3] + bv.y);
                    *(float2*)(out + (size_t)r * N_DIM + c)       = lo;
                    *(float2*)(out + (size_t)(r + 8) * N_DIM + c) = hi;
                    acc[mf][nf][0] = 0.f; acc[mf][nf][1] = 0.f;
                    acc[mf][nf][2] = 0.f; acc[mf][nf][3] = 0.f;
                }
            }
        }
    }
}

// ===================== host launcher =====================
extern "C" void kernel_launch(void* const* d_in, const int* in_sizes, int n_in,
                              void* d_out, int out_size) {
    (void)in_sizes; (void)n_in; (void)out_size;
    const float* x = (const float*)d_in[0];   // [8192,4096] f32
    const float* w = (const float*)d_in[1];   // [4096,4096] f32
    const float* b = (const float*)d_in[2];   // [4096] f32
    float* y = (float*)d_out;                 // [8192,4096] f32

    static __half* a16_ptr = nullptr;
    static __half* w16_ptr = nullptr;
    static int nsm = 0;
    if (!a16_ptr) {
        cudaGetSymbolAddress((void**)&a16_ptr, g_A16);
        cudaGetSymbolAddress((void**)&w16_ptr, g_W16);
        cudaDeviceGetAttribute(&nsm, cudaDevAttrMultiProcessorCount, 0);
        if (nsm <= 0 || nsm > NTILES) nsm = 148;
    }

    cvt_all_f32_to_f16<<<(NA4 + NW4) / 256, 256>>>(
        (const float4*)x, (const float4*)w, a16_ptr, w16_ptr);

    cudaFuncSetAttribute(linear_f16_hmma,
                         cudaFuncAttributeMaxDynamicSharedMemorySize, SMEM_TOTAL);
    linear_f16_hmma<<<nsm, NTHREADS, SMEM_TOTAL>>>(b, y);
}

// round 15
// speedup vs baseline: 1.1581x; 1.1405x over previous
#include <cuda_runtime.h>
#include <cuda_fp16.h>
#include <cstdint>

// ===================== problem dims (fixed) =====================
#define M_DIM 8192
#define N_DIM 4096
#define K_DIM 4096

// CTA tile 128(M) x 256(N), K-stage 64 halves (128B rows, SW128 swizzle)
// PERSISTENT CTAs, 4-stage cp.async ring, R12 sync protocol (CTA-wide
// noinc FULL + per-thread EMPTY arrives). NEW vs R12: SMSP warp pairs
// (wid, wid+4) process the 4 kk sub-blocks in ROTATED order so their
// LDSM dependency heads anti-align and the HMMA pipe stays fed.
#define TILE_M 128
#define TILE_N 256
#define KT 64
#define NK (K_DIM / KT)            // 64  (iterations per tile)
#define STAGES 4
#define NTHREADS 256               // 8 warps: 2(M) x 4(N), warp tile 64x64
#define NTILES 1024                // 64 mtiles x 16 ntiles

// ===================== static fp16 scratch (inputs arrive as f32) ==========
__device__ __half g_A16[(size_t)M_DIM * K_DIM];   // 64 MiB
__device__ __half g_W16[(size_t)N_DIM * K_DIM];   // 32 MiB

// ===================== SMEM layout (bytes) ======================
#define SM_FULL(s)  ((s) * 8)            // 0..31
#define SM_EMPTY(s) (32 + (s) * 8)       // 32..63
#define SM_STAGE0 1024
#define A_STAGE_BYTES (TILE_M * 128)     // 16384
#define B_STAGE_BYTES (TILE_N * 128)     // 32768
#define STAGE_BYTES (A_STAGE_BYTES + B_STAGE_BYTES)   // 49152
#define SM_A(s) (SM_STAGE0 + (s) * STAGE_BYTES)
#define SM_B(s) (SM_A(s) + A_STAGE_BYTES)
#define SMEM_TOTAL (SM_STAGE0 + STAGES * STAGE_BYTES) // 197632

// ===================== device helpers =====================
static __device__ __forceinline__ uint32_t smem_u32(const void* p) {
    uint32_t a;
    asm("{ .reg .u64 t; cvta.to.shared.u64 t, %1; cvt.u32.u64 %0, t; }"
        : "=r"(a) : "l"(p));
    return a;
}

static __device__ __forceinline__ uint32_t sw128(uint32_t off) {
    return off ^ ((off >> 3) & 0x70);
}

static __device__ __forceinline__ void cp_async16(uint32_t saddr, const void* gaddr) {
    asm volatile("cp.async.cg.shared.global [%0], [%1], 16;"
        :: "r"(saddr), "l"(gaddr) : "memory");
}

#define MBARRIER_INIT(addr, cnt) \
    asm volatile("mbarrier.init.shared.b64 [%0], %1;" \
        :: "r"((uint32_t)(addr)), "r"((uint32_t)(cnt)) : "memory")

#define MBARRIER_ARRIVE(addr) \
    asm volatile("mbarrier.arrive.shared.b64 _, [%0];" \
        :: "r"((uint32_t)(addr)) : "memory")

// arrive (counting against the INIT count: .noinc) when all this thread's
// prior cp.asyncs have completed.
#define CPASYNC_MBAR_ARRIVE(addr) \
    asm volatile("cp.async.mbarrier.arrive.noinc.shared::cta.b64 [%0];" \
        :: "r"((uint32_t)(addr)) : "memory")

#define MBARRIER_WAIT_PARITY(addr, parity) do {                                   \
    uint32_t _mbar = (uint32_t)(addr);                                            \
    uint32_t _par  = (uint32_t)(parity);                                          \
    uint32_t _done;                                                               \
    asm volatile(                                                                 \
        "{\n\t.reg .pred p;\n\t"                                                  \
        "mbarrier.try_wait.parity.acquire.cta.shared::cta.b64 p, [%1], %2;\n\t"   \
        "selp.b32 %0, 1, 0, p;\n\t}"                                              \
        : "=r"(_done) : "r"(_mbar), "r"(_par) : "memory");                        \
    if (!_done) {                                                                 \
        asm volatile(                                                             \
            "{\n\t.reg .pred P1;\n\t"                                             \
            "WAIT_LOOP_%=:\n\t"                                                   \
            "mbarrier.try_wait.parity.acquire.cta.shared::cta.b64 P1, [%0], %1, 0x989680;\n\t" \
            "@P1 bra.uni WAIT_DONE_%=;\n\t"                                       \
            "bra.uni WAIT_LOOP_%=;\n\t"                                           \
            "WAIT_DONE_%=:\n\t}"                                                  \
            :: "r"(_mbar), "r"(_par) : "memory");                                 \
    }                                                                             \
} while (0)

static __device__ __forceinline__ void ldsm_x4(uint32_t addr,
    uint32_t& r0, uint32_t& r1, uint32_t& r2, uint32_t& r3) {
    asm volatile("ldmatrix.sync.aligned.m8n8.x4.shared.b16 {%0,%1,%2,%3}, [%4];"
        : "=r"(r0), "=r"(r1), "=r"(r2), "=r"(r3) : "r"(addr));
}

static __device__ __forceinline__ void mma16816(
    float& c0, float& c1, float& c2, float& c3,
    uint32_t a0, uint32_t a1, uint32_t a2, uint32_t a3,
    uint32_t b0, uint32_t b1) {
    asm volatile(
        "mma.sync.aligned.m16n8k16.row.col.f32.f16.f16.f32 "
        "{%0,%1,%2,%3}, {%4,%5,%6,%7}, {%8,%9}, {%0,%1,%2,%3};"
        : "+f"(c0), "+f"(c1), "+f"(c2), "+f"(c3)
        : "r"(a0), "r"(a1), "r"(a2), "r"(a3), "r"(b0), "r"(b1));
}

static __device__ __forceinline__ float h_round(float x) {
    return __half2float(__float2half_rn(x));
}

// ===================== fused f32 -> f16 conversion (single launch) =========
#define NA4 ((M_DIM * K_DIM) / 4)          // 8388608
#define NW4 ((N_DIM * K_DIM) / 4)          // 4194304
__global__ void __launch_bounds__(256) cvt_all_f32_to_f16(
    const float4* __restrict__ inA, const float4* __restrict__ inW,
    __half* __restrict__ oA, __half* __restrict__ oW) {
    const int i = blockIdx.x * blockDim.x + threadIdx.x;
    const float4* src; __half* dst; int j;
    if (i < NA4) { src = inA; dst = oA; j = i; }
    else         { src = inW; dst = oW; j = i - NA4; }
    const float4 v = src[j];
    const __half2 h0 = __floats2half2_rn(v.x, v.y);
    const __half2 h1 = __floats2half2_rn(v.z, v.w);
    uint2 pk;
    pk.x = reinterpret_cast<const uint32_t&>(h0);
    pk.y = reinterpret_cast<const uint32_t&>(h1);
    *(uint2*)(dst + (size_t)j * 4) = pk;
}

// ===================== GEMM kernel (persistent) =====================
// 256 threads = 8 warps as 2(M) x 4(N); warp tile 64x64, f32 accumulate.
__global__ void __launch_bounds__(NTHREADS, 1) linear_f16_hmma(
    const float* __restrict__ bias,  // [4096] f32
    float* __restrict__ out)         // [8192, 4096] f32
{
    extern __shared__ char smem[];
    const uint32_t sb = smem_u32(smem);
    const int tid  = threadIdx.x;
    const int wid  = tid >> 5;
    const int lane = tid & 31;
    const int warp_m = wid & 1;      // 0..1
    const int warp_n = wid >> 1;     // 0..3
    const int bid  = blockIdx.x;
    const int nsm  = gridDim.x;

    // kk-order stagger: SMSP partners (wid, wid+4) differ in (wid>>2)&1.
    // Rotating kk by 2 anti-aligns their LDSM dependency heads.
    const int kk_stag = (wid >> 2) & 1;   // 0 or 1 -> rotate by 0 or 2

    // tiles handled by this CTA: bid, bid+nsm, ... < NTILES
    const int ntiles_cta = (NTILES - bid + nsm - 1) / nsm;
    const int niter = ntiles_cta * NK;

    // ---- init: mbarriers (tid 0) ----
    if (tid == 0) {
        #pragma unroll
        for (int s = 0; s < STAGES; ++s) {
            MBARRIER_INIT(sb + SM_FULL(s),  NTHREADS);
            MBARRIER_INIT(sb + SM_EMPTY(s), NTHREADS);
        }
    }
    __syncthreads();   // barriers visible; only CTA-wide sync in kernel

    const char* const Aall = (const char*)g_A16;
    const char* const Ball = (const char*)g_W16;

    // -------- stage loader for flat iteration `it`: 3072 x 16B chunks ------
    auto load_stage = [&](int it) {
        const int s  = it & (STAGES - 1);
        const int lt = it >> 6;                 // local tile index
        const int kt = it & (NK - 1);
        const int gt = bid + lt * nsm;          // global tile
        const int mt = gt >> 4, nt = gt & 15;
        const char* Abase = Aall + (size_t)(mt * TILE_M) * (K_DIM * 2);
        const char* Bbase = Ball + (size_t)(nt * TILE_N) * (K_DIM * 2);
        const size_t kbyte = (size_t)kt * (KT * 2);
        const uint32_t a_s = sb + SM_A(s);
        const uint32_t b_s = sb + SM_B(s);
        #pragma unroll
        for (int i = 0; i < 12; ++i) {
            const int c = tid + i * NTHREADS;
            if (c < 1024) {                       // A: 128 rows x 8 chunks
                const int row = c >> 3, ci = c & 7;
                const char* g = Abase + (size_t)row * (K_DIM * 2) + kbyte + ci * 16;
                cp_async16(a_s + sw128((uint32_t)(row * 128 + ci * 16)), g);
            } else {                              // B: 256 rows x 8 chunks
                const int c2 = c - 1024;
                const int row = c2 >> 3, ci = c2 & 7;
                const char* g = Bbase + (size_t)row * (K_DIM * 2) + kbyte + ci * 16;
                cp_async16(b_s + sw128((uint32_t)(row * 128 + ci * 16)), g);
            }
        }
        CPASYNC_MBAR_ARRIVE(sb + SM_FULL(s));
    };

    // -------- f32 accumulators: warp tile 64(M) x 64(N) --------
    float acc[4][8][4];
    #pragma unroll
    for (int mf = 0; mf < 4; ++mf)
        #pragma unroll
        for (int nf = 0; nf < 8; ++nf)
            #pragma unroll
            for (int i = 0; i < 4; ++i) acc[mf][nf][i] = 0.f;

    // per-lane ldmatrix address components
    const int a_row  = warp_m * 64 + (lane & 15);
    const int a_koff = (lane >> 4) * 16;
    const int b_row  = warp_n * 64 + ((lane >> 4) << 3) + (lane & 7);
    const int b_koff = ((lane >> 3) & 1) * 16;

    // -------- prologue: fill 3 stages --------
    if (0 < niter) load_stage(0);
    if (1 < niter) load_stage(1);
    if (2 < niter) load_stage(2);

    // -------- flat main loop over all tiles: ring never drains --------
    for (int it = 0; it < niter; ++it) {
        // produce iteration it+3 (slot last consumed as it-1)
        const int ld = it + 3;
        if (ld < niter) {
            if (ld >= STAGES) {   // slot has a previous lap to drain
                MBARRIER_WAIT_PARITY(sb + SM_EMPTY(ld & (STAGES - 1)),
                                     ((ld >> 2) - 1) & 1);
            }
            load_stage(ld);
        }

        // consume iteration it
        const int s = it & (STAGES - 1);
        MBARRIER_WAIT_PARITY(sb + SM_FULL(s), (it >> 2) & 1);

        const uint32_t aB = sb + SM_A(s);
        const uint32_t bB = sb + SM_B(s);

        #pragma unroll
        for (int kk = 0; kk < 4; ++kk) {
            // rotated kk order per SMSP partner (accumulation order-invariant)
            const int kc = ((kk + kk_stag * 2) & 3) * 32;

            uint32_t a[4][4];
            #pragma unroll
            for (int mf = 0; mf < 4; ++mf) {
                const uint32_t addr = aB +
                    sw128((uint32_t)((a_row + mf * 16) * 128 + kc + a_koff));
                ldsm_x4(addr, a[mf][0], a[mf][1], a[mf][2], a[mf][3]);
            }
            uint32_t b[4][4];
            #pragma unroll
            for (int nf2 = 0; nf2 < 4; ++nf2) {
                const uint32_t addr = bB +
                    sw128((uint32_t)((b_row + nf2 * 16) * 128 + kc + b_koff));
                ldsm_x4(addr, b[nf2][0], b[nf2][1], b[nf2][2], b[nf2][3]);
            }
            #pragma unroll
            for (int mf = 0; mf < 4; ++mf) {
                #pragma unroll
                for (int nf = 0; nf < 8; ++nf) {
                    const uint32_t b0 = b[nf >> 1][(nf & 1) * 2 + 0];
                    const uint32_t b1 = b[nf >> 1][(nf & 1) * 2 + 1];
                    mma16816(acc[mf][nf][0], acc[mf][nf][1],
                             acc[mf][nf][2], acc[mf][nf][3],
                             a[mf][0], a[mf][1], a[mf][2], a[mf][3], b0, b1);
                }
            }
        }

        // done reading this stage
        MBARRIER_ARRIVE(sb + SM_EMPTY(s));

        // -------- tile boundary: epilogue + acc reset --------
        if ((it & (NK - 1)) == NK - 1) {
            const int gt = bid + (it >> 6) * nsm;
            const int m0 = (gt >> 4) * TILE_M;
            const int n0 = (gt & 15) * TILE_N;

            const int row0 = m0 + warp_m * 64 + (lane >> 2);
            const int col0 = n0 + warp_n * 64 + (lane & 3) * 2;
            const int bcol = warp_n * 64 + (lane & 3) * 2;

            #pragma unroll
            for (int mf = 0; mf < 4; ++mf) {
                #pragma unroll
                for (int nf = 0; nf < 8; ++nf) {
                    const float2 bv = *(const float2*)(bias + n0 + bcol + nf * 8);
                    const int r = row0 + mf * 16;
                    const int c = col0 + nf * 8;
                    float2 lo, hi;
                    lo.x = h_round(acc[mf][nf][0] + bv.x);
                    lo.y = h_round(acc[mf][nf][1] + bv.y);
                    hi.x = h_round(acc[mf][nf][2] + bv.x);
                    hi.y = h_round(acc[mf][nf][3] + bv.y);
                    *(float2*)(out + (size_t)r * N_DIM + c)       = lo;
                    *(float2*)(out + (size_t)(r + 8) * N_DIM + c) = hi;
                    acc[mf][nf][0] = 0.f; acc[mf][nf][1] = 0.f;
                    acc[mf][nf][2] = 0.f; acc[mf][nf][3] = 0.f;
                }
            }
        }
    }
}

// ===================== host launcher =====================
extern "C" void kernel_launch(void* const* d_in, const int* in_sizes, int n_in,
                              void* d_out, int out_size) {
    (void)in_sizes; (void)n_in; (void)out_size;
    const float* x = (const float*)d_in[0];   // [8192,4096] f32
    const float* w = (const float*)d_in[1];   // [4096,4096] f32
    const float* b = (const float*)d_in[2];   // [4096] f32
    float* y = (float*)d_out;                 // [8192,4096] f32

    static __half* a16_ptr = nullptr;
    static __half* w16_ptr = nullptr;
    static int nsm = 0;
    if (!a16_ptr) {
        cudaGetSymbolAddress((void**)&a16_ptr, g_A16);
        cudaGetSymbolAddress((void**)&w16_ptr, g_W16);
        cudaDeviceGetAttribute(&nsm, cudaDevAttrMultiProcessorCount, 0);
        if (nsm <= 0 || nsm > NTILES) nsm = 148;
    }

    cvt_all_f32_to_f16<<<(NA4 + NW4) / 256, 256>>>(
        (const float4*)x, (const float4*)w, a16_ptr, w16_ptr);

    cudaFuncSetAttribute(linear_f16_hmma,
                         cudaFuncAttributeMaxDynamicSharedMemorySize, SMEM_TOTAL);
    linear_f16_hmma<<<nsm, NTHREADS, SMEM_TOTAL>>>(b, y);
}